// round 16
// baseline (speedup 1.0000x reference)
#include <cuda_runtime.h>
#include <cuda_bf16.h>
#include <math.h>
#include <stdint.h>

#define BB 8
#define SS 2048
#define HH 16
#define HD 64
#define DD 1024
#define MM (BB*SS)          /* 16384 rows */
#define CH 32               /* scan chunks per sequence */
#define CLEN (SS/CH)        /* 64 steps per chunk */

#define KC 32               /* K-chunk per SMEM stage */
#define NKT (DD/KC)         /* 32 stages */
#define STAGE_BYTES 32768   /* A 16KB + B 16KB (hi|lo packed in 128B rows) */
#define NSTAGE 3
#define DSMEM_BYTES (NSTAGE*STAGE_BYTES + 128)

// ---------------- scratch (static device memory; no allocs) ----------------
// Spectra stored TRANSPOSED: g_qkv[which][(b*1024 + col)][s], col = h*64+p.
__device__ float  g_qkv[3][(size_t)MM*DD];
__device__ float2 g_cs [(size_t)BB*HH*CH*32];              // chunk sums; slot0=(bin0,bin32)
__device__ __nv_bfloat16 g_xhi[(size_t)MM*DD];             // X split hi
__device__ __nv_bfloat16 g_xlo[(size_t)MM*DD];             // X split lo
__device__ __nv_bfloat16 g_wthi[3][(size_t)DD*DD];         // (W*F)^T split hi [N][K]
__device__ __nv_bfloat16 g_wtlo[3][(size_t)DD*DD];         // (W*F)^T split lo [N][K]
__device__ float g_bias[3][DD];                            // transformed bias

// ------------------------------ PTX helpers -------------------------------
__device__ __forceinline__ uint32_t smem_u32(const void* p) {
    uint32_t a;
    asm("{ .reg .u64 t; cvta.to.shared.u64 t, %1; cvt.u32.u64 %0, t; }"
        : "=r"(a) : "l"(p));
    return a;
}
__device__ __forceinline__ void cp16(uint32_t dst, const void* src) {
    asm volatile("cp.async.cg.shared.global [%0], [%1], 16;"
                 :: "r"(dst), "l"(src) : "memory");
}
__device__ __forceinline__ void cp_commit() {
    asm volatile("cp.async.commit_group;" ::: "memory");
}
__device__ __forceinline__ void cp_wait1() {
    asm volatile("cp.async.wait_group 1;" ::: "memory");
}
__device__ __forceinline__ void ldsm4(uint32_t& r0, uint32_t& r1, uint32_t& r2,
                                      uint32_t& r3, uint32_t addr) {
    asm volatile("ldmatrix.sync.aligned.m8n8.x4.shared.b16 {%0,%1,%2,%3}, [%4];"
                 : "=r"(r0), "=r"(r1), "=r"(r2), "=r"(r3) : "r"(addr));
}
__device__ __forceinline__ void mma_bf16(float* c, const uint32_t* a, const uint32_t* b) {
    asm volatile("mma.sync.aligned.m16n8k16.row.col.f32.bf16.bf16.f32 "
                 "{%0,%1,%2,%3},{%4,%5,%6,%7},{%8,%9},{%0,%1,%2,%3};"
                 : "+f"(c[0]), "+f"(c[1]), "+f"(c[2]), "+f"(c[3])
                 : "r"(a[0]), "r"(a[1]), "r"(a[2]), "r"(a[3]),
                   "r"(b[0]), "r"(b[1]));
}
__device__ __forceinline__ float getf(const float4 v, int u) {
    return u == 0 ? v.x : (u == 1 ? v.y : (u == 2 ? v.z : v.w));
}

// ---------------------------------------------------------------------------
// Convert X (fp32) -> bf16 hi/lo pair
// ---------------------------------------------------------------------------
__global__ __launch_bounds__(256)
void convert_x_kernel(const float* __restrict__ X)
{
    const size_t total = (size_t)MM * DD / 4;
    for (size_t i = blockIdx.x * 256 + threadIdx.x; i < total; i += (size_t)gridDim.x * 256) {
        float4 f = ((const float4*)X)[i];
        __nv_bfloat16 h0 = __float2bfloat16(f.x);
        __nv_bfloat16 h1 = __float2bfloat16(f.y);
        __nv_bfloat16 h2 = __float2bfloat16(f.z);
        __nv_bfloat16 h3 = __float2bfloat16(f.w);
        __nv_bfloat16 l0 = __float2bfloat16(f.x - __bfloat162float(h0));
        __nv_bfloat16 l1 = __float2bfloat16(f.y - __bfloat162float(h1));
        __nv_bfloat16 l2 = __float2bfloat16(f.z - __bfloat162float(h2));
        __nv_bfloat16 l3 = __float2bfloat16(f.w - __bfloat162float(h3));
        ((__nv_bfloat162*)g_xhi)[i * 2 + 0] = __nv_bfloat162(h0, h1);
        ((__nv_bfloat162*)g_xhi)[i * 2 + 1] = __nv_bfloat162(h2, h3);
        ((__nv_bfloat162*)g_xlo)[i * 2 + 0] = __nv_bfloat162(l0, l1);
        ((__nv_bfloat162*)g_xlo)[i * 2 + 1] = __nv_bfloat162(l2, l3);
    }
}

// ---------------------------------------------------------------------------
// W' = W * F (per-head packed real-DFT), output transposed [N][K], split hi/lo.
// Packing per head: col p in [0,32] = re(bin p); p in [33,63] = im(bin p-32).
// ---------------------------------------------------------------------------
__global__ __launch_bounds__(256)
void wtransform_kernel(const float* __restrict__ Wq,
                       const float* __restrict__ Wk,
                       const float* __restrict__ Wv)
{
    __shared__ float sW[64][65];   // [t][kk]
    __shared__ float sB[64][65];   // [p][t]
    const int which = blockIdx.z;
    const int h = blockIdx.y;
    const int k0 = blockIdx.x * 64;
    const float* W = (which == 0) ? Wq : (which == 1) ? Wk : Wv;
    const int tid = threadIdx.x;

    for (int e = tid; e < 4096; e += 256) {
        const int p = e >> 6, t = e & 63;
        const int bin = (p <= 32) ? p : (p - 32);
        float sn, cs;
        sincosf(6.2831853071795864f * (float)((bin * t) & 63) / 64.f, &sn, &cs);
        sB[p][t] = (p <= 32) ? cs : -sn;
    }
#pragma unroll
    for (int pass = 0; pass < 16; pass++) {
        const int kk = pass * 4 + (tid >> 6);
        const int t = tid & 63;
        sW[t][kk] = W[(size_t)(k0 + kk) * DD + h * 64 + t];
    }
    __syncthreads();

    for (int e = tid; e < 4096; e += 256) {
        const int p = e >> 6, kk = e & 63;
        float acc = 0.f;
#pragma unroll 16
        for (int t = 0; t < 64; t++)
            acc = fmaf(sB[p][t], sW[t][kk], acc);
        const __nv_bfloat16 hi = __float2bfloat16(acc);
        const __nv_bfloat16 lo = __float2bfloat16(acc - __bfloat162float(hi));
        const size_t o = (size_t)(h * 64 + p) * DD + k0 + kk;
        g_wthi[which][o] = hi;
        g_wtlo[which][o] = lo;
    }
}

// ---------------------------------------------------------------------------
// Transformed bias: b' = b * F (same packing). grid 3, block 256.
// ---------------------------------------------------------------------------
__global__ __launch_bounds__(256)
void btransform_kernel(const float* __restrict__ bq,
                       const float* __restrict__ bk,
                       const float* __restrict__ bv)
{
    const int which = blockIdx.x;
    const float* b = (which == 0) ? bq : (which == 1) ? bk : bv;
    const int tid = threadIdx.x;
#pragma unroll
    for (int i = 0; i < 4; i++) {
        const int n = tid + i * 256;
        const int h = n >> 6, p = n & 63;
        const int bin = (p <= 32) ? p : (p - 32);
        float acc = 0.f;
        for (int t = 0; t < 64; t++) {
            float sn, cs;
            sincosf(6.2831853071795864f * (float)((bin * t) & 63) / 64.f, &sn, &cs);
            acc = fmaf(b[h * 64 + t], (p <= 32) ? cs : -sn, acc);
        }
        g_bias[which][n] = acc;
    }
}

// ---------------------------------------------------------------------------
// Split-bf16 HMMA GEMM: CTA 128x128, 4 warps (2x2), warp tile 64x64.
// 3-stage cp.async ring, SW128 XOR swizzle, one barrier per K-tile.
// R14-champion mainloop: single copy burst issued after the FIRST MMA batch.
// Epilogue writes TRANSPOSED spectra: T[(b*1024+col)*SS + s].
// ---------------------------------------------------------------------------
__device__ __forceinline__ void copy_stage(uint32_t sA, uint32_t sB, int which,
                                           int rowB, int colB, int kt, int tid)
{
#pragma unroll
    for (int i = 0; i < 8; i++) {
        const int id = tid + i * 128;
        const int r = id >> 3, c = id & 7;
        const __nv_bfloat16* g = (c < 4) ? g_xhi : g_xlo;
        const void* src = g + (size_t)(rowB + r) * DD + kt * KC + (c & 3) * 8;
        cp16(sA + r * 128 + ((c ^ (r & 7)) << 4), src);
    }
#pragma unroll
    for (int i = 0; i < 8; i++) {
        const int id = tid + i * 128;
        const int r = id >> 3, c = id & 7;
        const __nv_bfloat16* g = (c < 4) ? g_wthi[which] : g_wtlo[which];
        const void* src = g + (size_t)(colB + r) * DD + kt * KC + (c & 3) * 8;
        cp16(sB + r * 128 + ((c ^ (r & 7)) << 4), src);
    }
}

__global__ __launch_bounds__(128)
void mma_gemm_kernel()
{
    extern __shared__ __align__(16) char dsm[];
    const int tid = threadIdx.x;
    const int wid = tid >> 5, lane = tid & 31;
    const int wm = wid & 1, wn = wid >> 1;   // 2x2 warp grid
    const int which = blockIdx.z;
    const int rowB = blockIdx.y * 128;
    const int colB = blockIdx.x * 128;

    uint32_t sbase = smem_u32(dsm);
    sbase = (sbase + 127u) & ~127u;

    float C[4][8][4];
#pragma unroll
    for (int mt = 0; mt < 4; mt++)
#pragma unroll
        for (int nt = 0; nt < 8; nt++)
#pragma unroll
            for (int j = 0; j < 4; j++) C[mt][nt][j] = 0.f;

    copy_stage(sbase, sbase + 16384, which, rowB, colB, 0, tid);
    cp_commit();
    copy_stage(sbase + STAGE_BYTES, sbase + STAGE_BYTES + 16384, which, rowB, colB, 1, tid);
    cp_commit();

    for (int kt = 0; kt < NKT; kt++) {
        cp_wait1();                  // group kt retired -> stage kt%3 data done
        __syncthreads();             // cross-thread visibility; slot (kt+2)%3 free
        const uint32_t sA = sbase + (kt % NSTAGE) * STAGE_BYTES;
        const uint32_t sB = sA + 16384;

        bool copied = false;
#pragma unroll
        for (int ks = 0; ks < 2; ks++) {
            uint32_t a[2][4][4];
#pragma unroll
            for (int h = 0; h < 2; h++)
#pragma unroll
                for (int mt = 0; mt < 4; mt++) {
                    const int row = wm * 64 + mt * 16 + (lane & 15);
                    const int c = 2 * ks + (lane >> 4) + h * 4;
                    ldsm4(a[h][mt][0], a[h][mt][1], a[h][mt][2], a[h][mt][3],
                          sA + row * 128 + ((c ^ (row & 7)) << 4));
                }
#pragma unroll
            for (int nh = 0; nh < 2; nh++) {
                uint32_t b[2][4][2];
#pragma unroll
                for (int h = 0; h < 2; h++)
#pragma unroll
                    for (int pp = 0; pp < 2; pp++) {
                        const int p = nh * 2 + pp;
                        const int row = wn * 64 + p * 16 + ((lane >> 4) << 3) + (lane & 7);
                        const int c = 2 * ks + ((lane >> 3) & 1) + h * 4;
                        ldsm4(b[h][2 * pp][0], b[h][2 * pp][1],
                              b[h][2 * pp + 1][0], b[h][2 * pp + 1][1],
                              sB + row * 128 + ((c ^ (row & 7)) << 4));
                    }
#pragma unroll
                for (int mt = 0; mt < 4; mt++)
#pragma unroll
                    for (int nl = 0; nl < 4; nl++) {
                        float* acc = C[mt][nh * 4 + nl];
                        mma_bf16(acc, a[0][mt], b[0][nl]);  // hi*hi
                        mma_bf16(acc, a[0][mt], b[1][nl]);  // hi*lo
                        mma_bf16(acc, a[1][mt], b[0][nl]);  // lo*hi
                    }
                if (!copied) {
                    copied = true;
                    if (kt + 2 < NKT) {
                        const uint32_t dA = sbase + ((kt + 2) % NSTAGE) * STAGE_BYTES;
                        copy_stage(dA, dA + 16384, which, rowB, colB, kt + 2, tid);
                    }
                    cp_commit();     // uniform group indexing
                }
            }
        }
    }

    // Epilogue: transposed fp32 stores + transformed bias.
    // trow = b*1024 + col; T[trow*SS + s].
    float* Tg = &g_qkv[which][0];
    const float* bias = g_bias[which];
    const int bidx = rowB >> 11;                 // batch (tile never crosses)
    const int sw = (rowB & (SS - 1)) + wm * 64;  // s-base of this warp's rows
    const int cw = colB + wn * 64;
#pragma unroll
    for (int mt = 0; mt < 4; mt++) {
#pragma unroll
        for (int nt = 0; nt < 8; nt++) {
            const int s0 = sw + mt * 16 + (lane >> 2);
            const int col = cw + nt * 8 + (lane & 3) * 2;
            const float bx = bias[col], by = bias[col + 1];
            const size_t o0 = ((size_t)(bidx * 1024 + col)) * SS + s0;
            Tg[o0]           = C[mt][nt][0] + bx;
            Tg[o0 + SS]      = C[mt][nt][1] + by;
            Tg[o0 + 8]       = C[mt][nt][2] + bx;
            Tg[o0 + SS + 8]  = C[mt][nt][3] + by;
        }
    }
}

// ---------------------------------------------------------------------------
// Warp-scan lane model: lane j in [1,31] owns complex bin j (rows j, 32+j of
// the transposed layout); lane 0's pair (row 0, row 32) = the two REAL bins.
// All spectra rows are contiguous in s -> float4 loads cover 4 steps.
// ---------------------------------------------------------------------------
__device__ __forceinline__ float unit1(float x) {
    return x / (fabsf(x) + 1e-8f);
}
__device__ __forceinline__ float2 bindc(float kr, float ki, float vr, float vi) {
    const float ik = 1.f / (sqrtf(kr * kr + ki * ki) + 1e-8f);
    const float iv = 1.f / (sqrtf(vr * vr + vi * vi) + 1e-8f);
    const float s = ik * iv;
    return make_float2((kr * vr - ki * vi) * s, (kr * vi + ki * vr) * s);
}

// ---------------------------------------------------------------------------
// Fused chunk sums + exclusive scan. grid 128 (bh), block (32,16):
// warp ty handles chunks ty and ty+16 (reg headroom for float4 pipelines).
// ---------------------------------------------------------------------------
__global__ __launch_bounds__(512)
void bind_sum_scan_kernel()
{
    __shared__ float2 sums[CH][32];
    const int bh = blockIdx.x;
    const int ty = threadIdx.y;        // 0..15
    const int j  = threadIdx.x;
    const int b  = bh >> 4, h = bh & 15;
    const size_t rowR = (size_t)(b * 1024 + h * 64 + j) * SS;
    const size_t rowI = (size_t)(b * 1024 + h * 64 + 32 + j) * SS;
    const float* Kg = &g_qkv[1][0];
    const float* Vg = &g_qkv[2][0];

#pragma unroll
    for (int cc = 0; cc < 2; cc++) {
        const int c = ty + cc * 16;
        const float4* Kr = (const float4*)(Kg + rowR + c * CLEN);
        const float4* Ki = (const float4*)(Kg + rowI + c * CLEN);
        const float4* Vr = (const float4*)(Vg + rowR + c * CLEN);
        const float4* Vi = (const float4*)(Vg + rowI + c * CLEN);
        float2 acc = make_float2(0.f, 0.f);
#pragma unroll 4
        for (int g = 0; g < CLEN / 4; g++) {
            const float4 kr4 = Kr[g], ki4 = Ki[g], vr4 = Vr[g], vi4 = Vi[g];
#pragma unroll
            for (int u = 0; u < 4; u++) {
                const float kr = getf(kr4, u), ki = getf(ki4, u);
                const float vr = getf(vr4, u), vi = getf(vi4, u);
                if (j == 0) {
                    acc.x += unit1(kr) * unit1(vr);   // bin 0
                    acc.y += unit1(ki) * unit1(vi);   // bin 32
                } else {
                    const float2 w = bindc(kr, ki, vr, vi);
                    acc.x += w.x; acc.y += w.y;
                }
            }
        }
        sums[c][j] = acc;
    }
    __syncthreads();

#pragma unroll
    for (int cc = 0; cc < 2; cc++) {
        const int c = ty + cc * 16;
        float2 ex = make_float2(0.f, 0.f);
        for (int k = 0; k < c; k++) {
            const float2 t = sums[k][j];
            ex.x += t.x; ex.y += t.y;
        }
        g_cs[((size_t)bh * CH + c) * 32 + j] = ex;
    }
}

// ---------------------------------------------------------------------------
// Fused bind+scan+retrieve+IDFT, one WARP per (b,h,chunk). float4 loads
// (4 steps each) with one-group software pipeline; recurrence twiddle chains.
// ---------------------------------------------------------------------------
__global__ __launch_bounds__(32)
void scan_idft_kernel(float* __restrict__ out)
{
    __shared__ float2 sh[32];   // rf spectrum; sh[0] = (rf0, rf32)
    const int bh = blockIdx.x;
    const int c  = blockIdx.y;
    const int j  = threadIdx.x;
    const int b  = bh >> 4, h = bh & 15;
    const size_t rowR = (size_t)(b * 1024 + h * 64 + j) * SS + c * CLEN;
    const size_t rowI = (size_t)(b * 1024 + h * 64 + 32 + j) * SS + c * CLEN;

    const float4* Qr = (const float4*)(&g_qkv[0][0] + rowR);
    const float4* Qi = (const float4*)(&g_qkv[0][0] + rowI);
    const float4* Kr = (const float4*)(&g_qkv[1][0] + rowR);
    const float4* Ki = (const float4*)(&g_qkv[1][0] + rowI);
    const float4* Vr = (const float4*)(&g_qkv[2][0] + rowR);
    const float4* Vi = (const float4*)(&g_qkv[2][0] + rowI);

    float2 ax = g_cs[((size_t)bh * CH + c) * 32 + j];

    float c1, s1;
    sincosf(6.2831853071795864f * (float)j / 64.f, &s1, &c1);
    const float c2 = c1 * c1 - s1 * s1;
    const float s2 = 2.f * c1 * s1;
    const float sgn = (j & 1) ? -1.f : 1.f;

    float4 KR = Kr[0], KI = Ki[0], VR = Vr[0], VI = Vi[0], QR = Qr[0], QI = Qi[0];

    float* outBase = out + (size_t)(b * SS + c * CLEN) * DD + h * HD;

    for (int g = 0; g < CLEN / 4; g++) {
        float4 nKR = {}, nKI = {}, nVR = {}, nVI = {}, nQR = {}, nQI = {};
        if (g + 1 < CLEN / 4) {
            nKR = Kr[g + 1]; nKI = Ki[g + 1];
            nVR = Vr[g + 1]; nVI = Vi[g + 1];
            nQR = Qr[g + 1]; nQI = Qi[g + 1];
        }
#pragma unroll
        for (int u = 0; u < 4; u++) {
            const float kr = getf(KR, u), ki = getf(KI, u);
            const float vr = getf(VR, u), vi = getf(VI, u);
            const float qr = getf(QR, u), qi = getf(QI, u);
            if (j == 0) {
                ax.x += unit1(kr) * unit1(vr);
                ax.y += unit1(ki) * unit1(vi);
                sh[0] = make_float2(ax.x * unit1(qr), ax.y * unit1(qi));
            } else {
                const float2 w = bindc(kr, ki, vr, vi);
                ax.x += w.x; ax.y += w.y;
                const float iq = 1.f / (sqrtf(qr * qr + qi * qi) + 1e-8f);
                const float qru = qr * iq, qiu = qi * iq;
                sh[j] = make_float2(ax.x * qru + ax.y * qiu,
                                    ax.y * qru - ax.x * qiu);
            }
            __syncwarp();

            const float2 rf0 = sh[0];
            float So = 0.f;
            {
                float cr = c1, ci = s1;
#pragma unroll
                for (int t = 0; t < 16; t++) {
                    const float2 f = sh[1 + 2 * t];
                    So = fmaf(f.x, cr, So);
                    So = fmaf(-f.y, ci, So);
                    const float nc = cr * c2 - ci * s2;
                    const float ns = cr * s2 + ci * c2;
                    cr = nc; ci = ns;
                }
            }
            float Se = 0.f;
            {
                float cr = c2, ci = s2;
#pragma unroll
                for (int t = 0; t < 15; t++) {
                    const float2 f = sh[2 + 2 * t];
                    Se = fmaf(f.x, cr, Se);
                    Se = fmaf(-f.y, ci, Se);
                    const float nc = cr * c2 - ci * s2;
                    const float ns = cr * s2 + ci * c2;
                    cr = nc; ci = ns;
                }
            }
            const float base = rf0.x + sgn * rf0.y;
            float* o = outBase + (size_t)(g * 4 + u) * DD;
            o[j]      = (base + 2.f * (Se + So)) * (1.f / 64.f);
            o[j + 32] = (base + 2.f * (Se - So)) * (1.f / 64.f);
            __syncwarp();
        }
        KR = nKR; KI = nKI; VR = nVR; VI = nVI; QR = nQR; QI = nQI;
    }
}

// ---------------------------------------------------------------------------
extern "C" void kernel_launch(void* const* d_in, const int* in_sizes, int n_in,
                              void* d_out, int out_size)
{
    const float* x  = (const float*)d_in[0];
    const float* Wq = (const float*)d_in[1];
    const float* bq = (const float*)d_in[2];
    const float* Wk = (const float*)d_in[3];
    const float* bk = (const float*)d_in[4];
    const float* Wv = (const float*)d_in[5];
    const float* bv = (const float*)d_in[6];
    float* out = (float*)d_out;

    cudaFuncSetAttribute(mma_gemm_kernel,
                         cudaFuncAttributeMaxDynamicSharedMemorySize, DSMEM_BYTES);

    convert_x_kernel<<<4096, 256>>>(x);
    wtransform_kernel<<<dim3(DD / 64, HH, 3), 256>>>(Wq, Wk, Wv);
    btransform_kernel<<<3, 256>>>(bq, bk, bv);

    mma_gemm_kernel<<<dim3(DD / 128, MM / 128, 3), 128, DSMEM_BYTES>>>();

    bind_sum_scan_kernel<<<BB * HH, dim3(32, 16)>>>();
    scan_idft_kernel<<<dim3(BB * HH, CH), 32>>>(out);
}

// round 17
// speedup vs baseline: 1.0802x; 1.0802x over previous
#include <cuda_runtime.h>
#include <cuda_bf16.h>
#include <math.h>
#include <stdint.h>

#define BB 8
#define SS 2048
#define HH 16
#define HD 64
#define DD 1024
#define MM (BB*SS)          /* 16384 rows */
#define CH 32               /* scan chunks per sequence */
#define CLEN (SS/CH)        /* 64 steps per chunk */

#define KC 32               /* K-chunk per SMEM stage */
#define NKT (DD/KC)         /* 32 stages */
#define STAGE_BYTES 32768   /* A 16KB + B 16KB (hi|lo packed in 128B rows) */
#define NSTAGE 3
#define DSMEM_BYTES (NSTAGE*STAGE_BYTES + 128)

// ---------------- scratch (static device memory; no allocs) ----------------
__device__ float  g_qkv[3][(size_t)MM*DD];                 // q,k,v spectra (packed rdft)
__device__ float2 g_cs [(size_t)BB*HH*CH*32];              // chunk sums; slot0=(bin0,bin32)
__device__ __nv_bfloat16 g_xhi[(size_t)MM*DD];             // X split hi
__device__ __nv_bfloat16 g_xlo[(size_t)MM*DD];             // X split lo
__device__ __nv_bfloat16 g_wthi[3][(size_t)DD*DD];         // (W*F)^T split hi [N][K]
__device__ __nv_bfloat16 g_wtlo[3][(size_t)DD*DD];         // (W*F)^T split lo [N][K]
__device__ float g_bias[3][DD];                            // transformed bias

// ------------------------------ PTX helpers -------------------------------
__device__ __forceinline__ uint32_t smem_u32(const void* p) {
    uint32_t a;
    asm("{ .reg .u64 t; cvta.to.shared.u64 t, %1; cvt.u32.u64 %0, t; }"
        : "=r"(a) : "l"(p));
    return a;
}
__device__ __forceinline__ void cp16(uint32_t dst, const void* src) {
    asm volatile("cp.async.cg.shared.global [%0], [%1], 16;"
                 :: "r"(dst), "l"(src) : "memory");
}
__device__ __forceinline__ void cp_commit() {
    asm volatile("cp.async.commit_group;" ::: "memory");
}
__device__ __forceinline__ void cp_wait1() {
    asm volatile("cp.async.wait_group 1;" ::: "memory");
}
__device__ __forceinline__ void ldsm4(uint32_t& r0, uint32_t& r1, uint32_t& r2,
                                      uint32_t& r3, uint32_t addr) {
    asm volatile("ldmatrix.sync.aligned.m8n8.x4.shared.b16 {%0,%1,%2,%3}, [%4];"
                 : "=r"(r0), "=r"(r1), "=r"(r2), "=r"(r3) : "r"(addr));
}
__device__ __forceinline__ void mma_bf16(float* c, const uint32_t* a, const uint32_t* b) {
    asm volatile("mma.sync.aligned.m16n8k16.row.col.f32.bf16.bf16.f32 "
                 "{%0,%1,%2,%3},{%4,%5,%6,%7},{%8,%9},{%0,%1,%2,%3};"
                 : "+f"(c[0]), "+f"(c[1]), "+f"(c[2]), "+f"(c[3])
                 : "r"(a[0]), "r"(a[1]), "r"(a[2]), "r"(a[3]),
                   "r"(b[0]), "r"(b[1]));
}

// ---------------------------------------------------------------------------
// Convert X (fp32) -> bf16 hi/lo pair
// ---------------------------------------------------------------------------
__global__ __launch_bounds__(256)
void convert_x_kernel(const float* __restrict__ X)
{
    const size_t total = (size_t)MM * DD / 4;
    for (size_t i = blockIdx.x * 256 + threadIdx.x; i < total; i += (size_t)gridDim.x * 256) {
        float4 f = ((const float4*)X)[i];
        __nv_bfloat16 h0 = __float2bfloat16(f.x);
        __nv_bfloat16 h1 = __float2bfloat16(f.y);
        __nv_bfloat16 h2 = __float2bfloat16(f.z);
        __nv_bfloat16 h3 = __float2bfloat16(f.w);
        __nv_bfloat16 l0 = __float2bfloat16(f.x - __bfloat162float(h0));
        __nv_bfloat16 l1 = __float2bfloat16(f.y - __bfloat162float(h1));
        __nv_bfloat16 l2 = __float2bfloat16(f.z - __bfloat162float(h2));
        __nv_bfloat16 l3 = __float2bfloat16(f.w - __bfloat162float(h3));
        ((__nv_bfloat162*)g_xhi)[i * 2 + 0] = __nv_bfloat162(h0, h1);
        ((__nv_bfloat162*)g_xhi)[i * 2 + 1] = __nv_bfloat162(h2, h3);
        ((__nv_bfloat162*)g_xlo)[i * 2 + 0] = __nv_bfloat162(l0, l1);
        ((__nv_bfloat162*)g_xlo)[i * 2 + 1] = __nv_bfloat162(l2, l3);
    }
}

// ---------------------------------------------------------------------------
// W' = W * F (per-head packed real-DFT), output transposed [N][K], split hi/lo.
// Packing per head: col p in [0,32] = re(bin p); p in [33,63] = im(bin p-32).
// ---------------------------------------------------------------------------
__global__ __launch_bounds__(256)
void wtransform_kernel(const float* __restrict__ Wq,
                       const float* __restrict__ Wk,
                       const float* __restrict__ Wv)
{
    __shared__ float sW[64][65];   // [t][kk]
    __shared__ float sB[64][65];   // [p][t]
    const int which = blockIdx.z;
    const int h = blockIdx.y;
    const int k0 = blockIdx.x * 64;
    const float* W = (which == 0) ? Wq : (which == 1) ? Wk : Wv;
    const int tid = threadIdx.x;

    for (int e = tid; e < 4096; e += 256) {
        const int p = e >> 6, t = e & 63;
        const int bin = (p <= 32) ? p : (p - 32);
        float sn, cs;
        sincosf(6.2831853071795864f * (float)((bin * t) & 63) / 64.f, &sn, &cs);
        sB[p][t] = (p <= 32) ? cs : -sn;
    }
#pragma unroll
    for (int pass = 0; pass < 16; pass++) {
        const int kk = pass * 4 + (tid >> 6);
        const int t = tid & 63;
        sW[t][kk] = W[(size_t)(k0 + kk) * DD + h * 64 + t];
    }
    __syncthreads();

    for (int e = tid; e < 4096; e += 256) {
        const int p = e >> 6, kk = e & 63;
        float acc = 0.f;
#pragma unroll 16
        for (int t = 0; t < 64; t++)
            acc = fmaf(sB[p][t], sW[t][kk], acc);
        const __nv_bfloat16 hi = __float2bfloat16(acc);
        const __nv_bfloat16 lo = __float2bfloat16(acc - __bfloat162float(hi));
        const size_t o = (size_t)(h * 64 + p) * DD + k0 + kk;
        g_wthi[which][o] = hi;
        g_wtlo[which][o] = lo;
    }
}

// ---------------------------------------------------------------------------
// Transformed bias: b' = b * F (same packing). grid 3, block 256.
// ---------------------------------------------------------------------------
__global__ __launch_bounds__(256)
void btransform_kernel(const float* __restrict__ bq,
                       const float* __restrict__ bk,
                       const float* __restrict__ bv)
{
    const int which = blockIdx.x;
    const float* b = (which == 0) ? bq : (which == 1) ? bk : bv;
    const int tid = threadIdx.x;
#pragma unroll
    for (int i = 0; i < 4; i++) {
        const int n = tid + i * 256;
        const int h = n >> 6, p = n & 63;
        const int bin = (p <= 32) ? p : (p - 32);
        float acc = 0.f;
        for (int t = 0; t < 64; t++) {
            float sn, cs;
            sincosf(6.2831853071795864f * (float)((bin * t) & 63) / 64.f, &sn, &cs);
            acc = fmaf(b[h * 64 + t], (p <= 32) ? cs : -sn, acc);
        }
        g_bias[which][n] = acc;
    }
}

// ---------------------------------------------------------------------------
// Split-bf16 HMMA GEMM: CTA 128x128, 4 warps (2x2), warp tile 64x64.
// 3-stage cp.async ring, SW128 XOR swizzle, one barrier per K-tile.
// R14 champion: single copy burst issued after the FIRST MMA batch.
// ---------------------------------------------------------------------------
__device__ __forceinline__ void copy_stage(uint32_t sA, uint32_t sB, int which,
                                           int rowB, int colB, int kt, int tid)
{
#pragma unroll
    for (int i = 0; i < 8; i++) {
        const int id = tid + i * 128;
        const int r = id >> 3, c = id & 7;
        const __nv_bfloat16* g = (c < 4) ? g_xhi : g_xlo;
        const void* src = g + (size_t)(rowB + r) * DD + kt * KC + (c & 3) * 8;
        cp16(sA + r * 128 + ((c ^ (r & 7)) << 4), src);
    }
#pragma unroll
    for (int i = 0; i < 8; i++) {
        const int id = tid + i * 128;
        const int r = id >> 3, c = id & 7;
        const __nv_bfloat16* g = (c < 4) ? g_wthi[which] : g_wtlo[which];
        const void* src = g + (size_t)(colB + r) * DD + kt * KC + (c & 3) * 8;
        cp16(sB + r * 128 + ((c ^ (r & 7)) << 4), src);
    }
}

__global__ __launch_bounds__(128)
void mma_gemm_kernel()
{
    extern __shared__ __align__(16) char dsm[];
    const int tid = threadIdx.x;
    const int wid = tid >> 5, lane = tid & 31;
    const int wm = wid & 1, wn = wid >> 1;   // 2x2 warp grid
    const int which = blockIdx.z;
    const int rowB = blockIdx.y * 128;
    const int colB = blockIdx.x * 128;

    uint32_t sbase = smem_u32(dsm);
    sbase = (sbase + 127u) & ~127u;

    float C[4][8][4];
#pragma unroll
    for (int mt = 0; mt < 4; mt++)
#pragma unroll
        for (int nt = 0; nt < 8; nt++)
#pragma unroll
            for (int j = 0; j < 4; j++) C[mt][nt][j] = 0.f;

    copy_stage(sbase, sbase + 16384, which, rowB, colB, 0, tid);
    cp_commit();
    copy_stage(sbase + STAGE_BYTES, sbase + STAGE_BYTES + 16384, which, rowB, colB, 1, tid);
    cp_commit();

    for (int kt = 0; kt < NKT; kt++) {
        cp_wait1();                  // group kt retired -> stage kt%3 data done
        __syncthreads();             // cross-thread visibility; slot (kt+2)%3 free
        const uint32_t sA = sbase + (kt % NSTAGE) * STAGE_BYTES;
        const uint32_t sB = sA + 16384;

        bool copied = false;
#pragma unroll
        for (int ks = 0; ks < 2; ks++) {
            uint32_t a[2][4][4];
#pragma unroll
            for (int h = 0; h < 2; h++)
#pragma unroll
                for (int mt = 0; mt < 4; mt++) {
                    const int row = wm * 64 + mt * 16 + (lane & 15);
                    const int c = 2 * ks + (lane >> 4) + h * 4;
                    ldsm4(a[h][mt][0], a[h][mt][1], a[h][mt][2], a[h][mt][3],
                          sA + row * 128 + ((c ^ (row & 7)) << 4));
                }
#pragma unroll
            for (int nh = 0; nh < 2; nh++) {
                uint32_t b[2][4][2];
#pragma unroll
                for (int h = 0; h < 2; h++)
#pragma unroll
                    for (int pp = 0; pp < 2; pp++) {
                        const int p = nh * 2 + pp;
                        const int row = wn * 64 + p * 16 + ((lane >> 4) << 3) + (lane & 7);
                        const int c = 2 * ks + ((lane >> 3) & 1) + h * 4;
                        ldsm4(b[h][2 * pp][0], b[h][2 * pp][1],
                              b[h][2 * pp + 1][0], b[h][2 * pp + 1][1],
                              sB + row * 128 + ((c ^ (row & 7)) << 4));
                    }
#pragma unroll
                for (int mt = 0; mt < 4; mt++)
#pragma unroll
                    for (int nl = 0; nl < 4; nl++) {
                        float* acc = C[mt][nh * 4 + nl];
                        mma_bf16(acc, a[0][mt], b[0][nl]);  // hi*hi
                        mma_bf16(acc, a[0][mt], b[1][nl]);  // hi*lo
                        mma_bf16(acc, a[1][mt], b[0][nl]);  // lo*hi
                    }
                // Issue the next stage's copy AFTER the first MMA batch:
                // LSU burst overlaps tensor work.
                if (!copied) {
                    copied = true;
                    if (kt + 2 < NKT) {
                        const uint32_t dA = sbase + ((kt + 2) % NSTAGE) * STAGE_BYTES;
                        copy_stage(dA, dA + 16384, which, rowB, colB, kt + 2, tid);
                    }
                    cp_commit();     // unconditional: uniform group indexing
                }
            }
        }
    }

    // Epilogue: fp32 stores + transformed bias
    float* Cg = &g_qkv[which][0];
    const float* bias = g_bias[which];
    const int rw = rowB + wm * 64;
    const int cw = colB + wn * 64;
#pragma unroll
    for (int mt = 0; mt < 4; mt++) {
#pragma unroll
        for (int nt = 0; nt < 8; nt++) {
            const int r0 = rw + mt * 16 + (lane >> 2);
            const int col = cw + nt * 8 + (lane & 3) * 2;
            const float bx = bias[col], by = bias[col + 1];
            float2 o0 = make_float2(C[mt][nt][0] + bx, C[mt][nt][1] + by);
            float2 o1 = make_float2(C[mt][nt][2] + bx, C[mt][nt][3] + by);
            *(float2*)&Cg[(size_t)r0 * DD + col]       = o0;
            *(float2*)&Cg[(size_t)(r0 + 8) * DD + col] = o1;
        }
    }
}

// ---------------------------------------------------------------------------
// Warp-scan lane model: lane j in [1,31] owns complex bin j (cols j, 32+j);
// lane 0's pair (col 0, col 32) = the two REAL bins.
// ---------------------------------------------------------------------------
__device__ __forceinline__ float unit1(float x) {
    return x / (fabsf(x) + 1e-8f);
}
__device__ __forceinline__ float2 bindc(float kr, float ki, float vr, float vi) {
    const float ik = 1.f / (sqrtf(kr * kr + ki * ki) + 1e-8f);
    const float iv = 1.f / (sqrtf(vr * vr + vi * vi) + 1e-8f);
    const float s = ik * iv;
    return make_float2((kr * vr - ki * vi) * s, (kr * vi + ki * vr) * s);
}

// ---------------------------------------------------------------------------
// Fused chunk sums + exclusive scan. grid 128 (bh), block (32, 32):
// warp c computes chunk c's bind sum, then block-scan across chunks.
// (R14 champion version, unchanged.)
// ---------------------------------------------------------------------------
__global__ __launch_bounds__(1024)
void bind_sum_scan_kernel()
{
    __shared__ float2 sums[CH][32];
    const int bh = blockIdx.x;
    const int c  = threadIdx.y;
    const int j  = threadIdx.x;
    const int b  = bh >> 4, h = bh & 15;
    const int offR = h * 64 + j;
    const int offI = h * 64 + 32 + j;

    const float* K = &g_qkv[1][0];
    const float* V = &g_qkv[2][0];
    const size_t m0 = (size_t)(b * SS + c * CLEN);

    float kr = K[m0 * DD + offR], ki = K[m0 * DD + offI];
    float vr = V[m0 * DD + offR], vi = V[m0 * DD + offI];

    float2 acc = make_float2(0.f, 0.f);
    for (int sl = 0; sl < CLEN; sl++) {
        float krn = 0, kin = 0, vrn = 0, vin = 0;
        if (sl + 1 < CLEN) {
            const size_t m = m0 + sl + 1;
            krn = K[m * DD + offR]; kin = K[m * DD + offI];
            vrn = V[m * DD + offR]; vin = V[m * DD + offI];
        }
        if (j == 0) {
            acc.x += unit1(kr) * unit1(vr);   // bin 0
            acc.y += unit1(ki) * unit1(vi);   // bin 32
        } else {
            const float2 w = bindc(kr, ki, vr, vi);
            acc.x += w.x; acc.y += w.y;
        }
        kr = krn; ki = kin; vr = vrn; vi = vin;
    }
    sums[c][j] = acc;
    __syncthreads();

    float2 ex = make_float2(0.f, 0.f);
    for (int cc = 0; cc < c; cc++) {
        const float2 t = sums[cc][j];
        ex.x += t.x; ex.y += t.y;
    }
    g_cs[((size_t)bh * CH + c) * 32 + j] = ex;
}

// ---------------------------------------------------------------------------
// Fused bind+scan+retrieve+IDFT, one WARP per (b,h,chunk). Each lane makes
// TWO output samples (n, n+32) via the even/odd split. Recurrence twiddle
// chains (R14 champion version, unchanged).
// ---------------------------------------------------------------------------
__global__ __launch_bounds__(32)
void scan_idft_kernel(float* __restrict__ out)
{
    __shared__ float2 sh[32];   // rf spectrum; sh[0] = (rf0, rf32)
    const int bh = blockIdx.x;
    const int c  = blockIdx.y;
    const int j  = threadIdx.x;
    const int b  = bh >> 4, h = bh & 15;
    const int offR = h * 64 + j;
    const int offI = h * 64 + 32 + j;

    const float* Q = &g_qkv[0][0];
    const float* K = &g_qkv[1][0];
    const float* V = &g_qkv[2][0];
    const size_t m0 = (size_t)(b * SS + c * CLEN);

    float2 ax = g_cs[((size_t)bh * CH + c) * 32 + j];

    float c1, s1;
    sincosf(6.2831853071795864f * (float)j / 64.f, &s1, &c1);
    const float c2 = c1 * c1 - s1 * s1;
    const float s2 = 2.f * c1 * s1;
    const float sgn = (j & 1) ? -1.f : 1.f;

    float kr = K[m0 * DD + offR], ki = K[m0 * DD + offI];
    float vr = V[m0 * DD + offR], vi = V[m0 * DD + offI];
    float qr = Q[m0 * DD + offR], qi = Q[m0 * DD + offI];

    float* outBase = out + (size_t)(b * SS + c * CLEN) * DD + h * HD;

    for (int sl = 0; sl < CLEN; sl++) {
        float krn = 0, kin = 0, vrn = 0, vin = 0, qrn = 0, qin = 0;
        if (sl + 1 < CLEN) {
            const size_t m = m0 + sl + 1;
            krn = K[m * DD + offR]; kin = K[m * DD + offI];
            vrn = V[m * DD + offR]; vin = V[m * DD + offI];
            qrn = Q[m * DD + offR]; qin = Q[m * DD + offI];
        }
        if (j == 0) {
            ax.x += unit1(kr) * unit1(vr);
            ax.y += unit1(ki) * unit1(vi);
            sh[0] = make_float2(ax.x * unit1(qr), ax.y * unit1(qi));
        } else {
            const float2 w = bindc(kr, ki, vr, vi);
            ax.x += w.x; ax.y += w.y;
            const float iq = 1.f / (sqrtf(qr * qr + qi * qi) + 1e-8f);
            const float qru = qr * iq, qiu = qi * iq;
            sh[j] = make_float2(ax.x * qru + ax.y * qiu,
                                ax.y * qru - ax.x * qiu);
        }
        __syncwarp();

        const float2 rf0 = sh[0];
        float So = 0.f;
        {
            float cr = c1, ci = s1;
#pragma unroll
            for (int t = 0; t < 16; t++) {
                const float2 f = sh[1 + 2 * t];
                So = fmaf(f.x, cr, So);
                So = fmaf(-f.y, ci, So);
                const float nc = cr * c2 - ci * s2;
                const float ns = cr * s2 + ci * c2;
                cr = nc; ci = ns;
            }
        }
        float Se = 0.f;
        {
            float cr = c2, ci = s2;
#pragma unroll
            for (int t = 0; t < 15; t++) {
                const float2 f = sh[2 + 2 * t];
                Se = fmaf(f.x, cr, Se);
                Se = fmaf(-f.y, ci, Se);
                const float nc = cr * c2 - ci * s2;
                const float ns = cr * s2 + ci * c2;
                cr = nc; ci = ns;
            }
        }
        const float base = rf0.x + sgn * rf0.y;
        float* o = outBase + (size_t)sl * DD;
        o[j]      = (base + 2.f * (Se + So)) * (1.f / 64.f);
        o[j + 32] = (base + 2.f * (Se - So)) * (1.f / 64.f);
        __syncwarp();

        kr = krn; ki = kin; vr = vrn; vi = vin; qr = qrn; qi = qin;
    }
}

// ---------------------------------------------------------------------------
// Launch: event-fork so weight transforms (s1) overlap x conversion (s0);
// join before the single 3-matrix GEMM. (Fork pattern validated in R11.)
// ---------------------------------------------------------------------------
extern "C" void kernel_launch(void* const* d_in, const int* in_sizes, int n_in,
                              void* d_out, int out_size)
{
    const float* x  = (const float*)d_in[0];
    const float* Wq = (const float*)d_in[1];
    const float* bq = (const float*)d_in[2];
    const float* Wk = (const float*)d_in[3];
    const float* bk = (const float*)d_in[4];
    const float* Wv = (const float*)d_in[5];
    const float* bv = (const float*)d_in[6];
    float* out = (float*)d_out;

    cudaFuncSetAttribute(mma_gemm_kernel,
                         cudaFuncAttributeMaxDynamicSharedMemorySize, DSMEM_BYTES);

    cudaStream_t s0 = 0;
    cudaStream_t s1;
    cudaStreamCreateWithFlags(&s1, cudaStreamNonBlocking);
    cudaEvent_t eStart, eW;
    cudaEventCreateWithFlags(&eStart, cudaEventDisableTiming);
    cudaEventCreateWithFlags(&eW, cudaEventDisableTiming);

    cudaEventRecord(eStart, s0);
    cudaStreamWaitEvent(s1, eStart, 0);
    wtransform_kernel<<<dim3(DD / 64, HH, 3), 256, 0, s1>>>(Wq, Wk, Wv);
    btransform_kernel<<<3, 256, 0, s1>>>(bq, bk, bv);
    cudaEventRecord(eW, s1);

    convert_x_kernel<<<4096, 256, 0, s0>>>(x);
    cudaStreamWaitEvent(s0, eW, 0);

    mma_gemm_kernel<<<dim3(DD / 128, MM / 128, 3), 128, DSMEM_BYTES, s0>>>();

    bind_sum_scan_kernel<<<BB * HH, dim3(32, CH), 0, s0>>>();
    scan_idft_kernel<<<dim3(BB * HH, CH), 32, 0, s0>>>(out);
}